// round 10
// baseline (speedup 1.0000x reference)
#include <cuda_runtime.h>
#include <cstdint>

// GaussianSampler: R[b,c] = sum_{y,x} X[b,c,y,x] * gx[c,x] * gy[c,y] / norm
// R10 = R9 cp.async double-buffered pipeline with the OOB fix: compute-phase
// shared reads use float-element offsets 4t + {0,1024,2048,3072} (R8/R9
// wrongly used byte-offset values 4096/8192/12288 as element offsets, reading
// past the stage buffer -> illegal access).

#define NCH 1024
#define HH  64
#define WW  64
#define TPB 32          // tiles per block

__device__ __forceinline__ void cp16(uint32_t dst_smem, const void* src) {
    asm volatile("cp.async.cg.shared.global [%0], [%1], 16;\n"
                 :: "r"(dst_smem), "l"(src));
}

__global__ __launch_bounds__(256)
void gaussian_sampler_kernel(
    const float* __restrict__ X,     // [B, C, H, W]
    const float* __restrict__ wx,    // [C]
    const float* __restrict__ wy,    // [C]
    const float* __restrict__ wsx,   // [C]
    const float* __restrict__ wsy,   // [C]
    float* __restrict__ out)         // [B, C]
{
    __shared__ __align__(16) float buf[2][HH * WW];   // 2 x 16 KiB tiles
    __shared__ __align__(16) float gxs[2][WW];
    __shared__ __align__(16) float gys[2][HH];        // norm folded in
    __shared__ __align__(16) float red[8];

    const int t = threadIdx.x;
    const int tile0 = blockIdx.x * TPB;

    const uint32_t buf0 = (uint32_t)__cvta_generic_to_shared(&buf[0][0]);
    const uint32_t buf1 = (uint32_t)__cvta_generic_to_shared(&buf[1][0]);

    // Per-thread invariants: x = (4t)&63 fixed; y rows = (4t>>6) + 16k.
    const int x  = (4 * t) & 63;
    const int y0 = (4 * t) >> 6;

    // ---- issue async loads for one tile into stage s (byte offsets) ----
    auto issue_tile = [&](int tile, int s) {
        const char* src = (const char*)(X + (size_t)tile * (HH * WW));
        uint32_t dst = (s ? buf1 : buf0) + (uint32_t)t * 16u;
        cp16(dst,            src + t * 16);              // float4 j = t
        cp16(dst + 4096u,    src + (t + 256) * 16);      // j = t + 256
        cp16(dst + 8192u,    src + (t + 512) * 16);      // j = t + 512
        cp16(dst + 12288u,   src + (t + 768) * 16);      // j = t + 768
        asm volatile("cp.async.commit_group;\n" ::: "memory");
    };

    // ---- separable weights for one tile into stage s (threads < 128) ----
    auto weights_tile = [&](int tile, int s) {
        const int c = tile & (NCH - 1);
        if (t < 64) {
            float sx = wsx[c];
            float d = (-0.984375f + (float)t * 0.03125f) - wx[c];
            gxs[s][t] = __expf(-d * d / (2.0f * sx * sx));
        } else if (t < 128) {
            int i = t - 64;
            float sy = wsy[c];
            float sx = wsx[c];
            float d = (-0.984375f + (float)i * 0.03125f) - wy[c];
            float scale = 1.0f / (2.5066282746310002f * sx * sy * 1024.0f);
            gys[s][i] = __expf(-d * d / (2.0f * sy * sy)) * scale;
        }
    };

    // ---- prologue: start tile 0 in stage 0 ----
    issue_tile(tile0, 0);
    weights_tile(tile0, 0);

    for (int i = 0; i < TPB; i++) {
        const int s = i & 1;

        if (i + 1 < TPB) {
            issue_tile(tile0 + i + 1, s ^ 1);     // keep DRAM busy
            weights_tile(tile0 + i + 1, s ^ 1);
            asm volatile("cp.async.wait_group 1;\n" ::: "memory");
        } else {
            asm volatile("cp.async.wait_group 0;\n" ::: "memory");
        }
        __syncthreads();                           // tile i data + weights visible

        // ---- process tile i from shared (float-ELEMENT offsets) ----
        const float* bs = buf[s];
        float4 g  = *reinterpret_cast<const float4*>(&gxs[s][x]);
        float4 v0 = *reinterpret_cast<const float4*>(bs + 4 * t);          // j=t
        float4 v1 = *reinterpret_cast<const float4*>(bs + 4 * t + 1024);   // j=t+256
        float4 v2 = *reinterpret_cast<const float4*>(bs + 4 * t + 2048);   // j=t+512
        float4 v3 = *reinterpret_cast<const float4*>(bs + 4 * t + 3072);   // j=t+768

        float acc;
        acc  = gys[s][y0]      * (v0.x*g.x + v0.y*g.y + v0.z*g.z + v0.w*g.w);
        acc += gys[s][y0 + 16] * (v1.x*g.x + v1.y*g.y + v1.z*g.z + v1.w*g.w);
        acc += gys[s][y0 + 32] * (v2.x*g.x + v2.y*g.y + v2.z*g.z + v2.w*g.w);
        acc += gys[s][y0 + 48] * (v3.x*g.x + v3.y*g.y + v3.z*g.z + v3.w*g.w);

        #pragma unroll
        for (int off = 16; off > 0; off >>= 1)
            acc += __shfl_down_sync(0xffffffffu, acc, off);

        if ((t & 31) == 0) red[t >> 5] = acc;
        __syncthreads();

        if (t < 32) {
            float v = (t < 8) ? red[t] : 0.0f;
            #pragma unroll
            for (int off = 4; off > 0; off >>= 1)
                v += __shfl_down_sync(0xffffffffu, v, off);
            if (t == 0) out[tile0 + i] = v;
        }
        __syncthreads();   // protect red[] and stage buffers before reuse
    }
}

extern "C" void kernel_launch(void* const* d_in, const int* in_sizes, int n_in,
                              void* d_out, int out_size) {
    // metadata order: X, wx, wy, wsigmax, wsigmay, mask
    const float* X   = (const float*)d_in[0];
    const float* wx  = (const float*)d_in[1];
    const float* wy  = (const float*)d_in[2];
    const float* wsx = (const float*)d_in[3];
    const float* wsy = (const float*)d_in[4];
    // mask (d_in[5]) is all-true by construction; nonzero(size=C) gather is identity.
    float* out = (float*)d_out;

    const int B = in_sizes[0] / (NCH * HH * WW);   // 32
    const int ntiles = B * NCH;                    // 32768
    const int nblocks = ntiles / TPB;              // 1024

    gaussian_sampler_kernel<<<nblocks, 256>>>(X, wx, wy, wsx, wsy, out);
}

// round 11
// speedup vs baseline: 1.3756x; 1.3756x over previous
#include <cuda_runtime.h>

// GaussianSampler: R[b,c] = sum_{y,x} X[b,c,y,x] * exp(-(xs[x]-wx_c)^2/(2 sx^2))
//                                     * exp(-(ys[y]-wy_c)^2/(2 sy^2)) / norm
// norm = sqrt(2*pi) * sx * sy * H*W/4
// Separable weights: 64+64 __expf per block instead of 4096.
// Grid: one block per (b,c) pair = 32*1024 = 32768 blocks. Pure HBM stream of X (512 MiB).
//
// CONVERGED (R11 = R1): 10 rounds of variants (batch amortization, per-thread
// weights, L2 prefetch, MLP front-batching, 2-channel blocks, __ldcs,
// cp.async double-buffered pipeline) all land at or below this kernel's
// 6.95 TB/s. Runtime == bytes / measured-LTS-cap; the ~88% DRAM duty reading
// is the LTS-vs-DRAM spec gap, not recoverable slack.

#define NCH 1024
#define HH  64
#define WW  64

__global__ __launch_bounds__(256, 8)
void gaussian_sampler_kernel(
    const float* __restrict__ X,     // [B, C, H, W]
    const float* __restrict__ wx,    // [C]
    const float* __restrict__ wy,    // [C]
    const float* __restrict__ wsx,   // [C]
    const float* __restrict__ wsy,   // [C]
    float* __restrict__ out)         // [B, C]
{
    const int blk = blockIdx.x;          // = b*NCH + c
    const int c   = blk & (NCH - 1);

    __shared__ float gx[WW];
    __shared__ float gy[HH];
    __shared__ float s_scale;
    __shared__ float red[8];

    const int t = threadIdx.x;

    // coords: linspace(-63/64, 63/64, 64) -> coord[i] = -63/64 + i/32
    if (t < 64) {
        float s = wsx[c];
        float coord = -0.984375f + (float)t * 0.03125f;
        float d = coord - wx[c];
        gx[t] = __expf(-d * d / (2.0f * s * s));
    } else if (t < 128) {
        int i = t - 64;
        float s = wsy[c];
        float coord = -0.984375f + (float)i * 0.03125f;
        float d = coord - wy[c];
        gy[i] = __expf(-d * d / (2.0f * s * s));
    } else if (t == 128) {
        // 1 / (sqrt(2*pi) * sx * sy * H*W/4),  H*W/4 = 1024
        s_scale = 1.0f / (2.5066282746310002f * wsx[c] * wsy[c] * 1024.0f);
    }
    __syncthreads();

    // Each block reads its contiguous 16 KiB tile: X + blk*4096 floats.
    const float4* __restrict__ xp =
        reinterpret_cast<const float4*>(X + (size_t)blk * (HH * WW));

    float acc = 0.0f;
    #pragma unroll
    for (int it = 0; it < 4; it++) {
        int j = t + it * 256;            // float4 index in [0, 1024)
        float4 v = xp[j];
        int lin = j << 2;                // float index
        int y = lin >> 6;                // row
        int x = lin & 63;                // col (multiple of 4)
        float gyv = gy[y];
        acc += gyv * (v.x * gx[x] + v.y * gx[x + 1] +
                      v.z * gx[x + 2] + v.w * gx[x + 3]);
    }

    // Intra-warp reduce
    #pragma unroll
    for (int off = 16; off > 0; off >>= 1)
        acc += __shfl_down_sync(0xffffffffu, acc, off);

    if ((t & 31) == 0) red[t >> 5] = acc;
    __syncthreads();

    if (t < 8) {
        float v = red[t];
        #pragma unroll
        for (int off = 4; off > 0; off >>= 1)
            v += __shfl_down_sync(0x000000ffu, v, off);
        if (t == 0) out[blk] = v * s_scale;
    }
}

extern "C" void kernel_launch(void* const* d_in, const int* in_sizes, int n_in,
                              void* d_out, int out_size) {
    // metadata order: X, wx, wy, wsigmax, wsigmay, mask
    const float* X   = (const float*)d_in[0];
    const float* wx  = (const float*)d_in[1];
    const float* wy  = (const float*)d_in[2];
    const float* wsx = (const float*)d_in[3];
    const float* wsy = (const float*)d_in[4];
    // mask (d_in[5]) is all-true by construction; nonzero(size=C) gather is identity.
    float* out = (float*)d_out;

    const int B = in_sizes[0] / (NCH * HH * WW);   // 32
    const int nblocks = B * NCH;                   // 32768

    gaussian_sampler_kernel<<<nblocks, 256>>>(X, wx, wy, wsx, wsy, out);
}